// round 14
// baseline (speedup 1.0000x reference)
#include <cuda_runtime.h>
#include <cstdint>

// MatchSegmentation, single fused kernel, g-split occupancy build.
// matching = argmax_g S[k,g] (log2-space CE, monotone rescale); greedy dedup.
// TPB=448: half h = wid/7 owns g in [11h, 11h+11) (row 21 = zero dummy);
// warp w%7 owns k-triple. S per thread = 3x11. LDGSTS 3-stage ring; gt
// int->float once per tile; per g: 1 LDS.64 + 6 FMA. Warp reduce -> atomicAdd;
// last CTA finalizes + resets for graph replay.

#define KK   21            // predicted segments (== out_size)
#define EPSF 1e-6f
#define PIX  128           // pixels per tile
#define TPB  448           // 14 warps: (half, k-triple)
#define NBLK 296           // 2 CTAs/SM on 148 SMs
#define NST  3             // pipeline stages
#define GSP  11            // g's per half
#define GROW (KK+1)        // 22 gt rows in smem (row 21 = zero dummy)
#define ROWW (KK+1)
#define NENT (KK*ROWW)     // 462

__device__ float g_acc[NENT];   // zero at load; last CTA re-zeros each run
__device__ int   g_ctr;

// gt_instance is int32 0/1; uniform(0,1) float bits are never <= 1.
__device__ __forceinline__ bool looks_like_gt(const void* p) {
    const unsigned* u = (const unsigned*)p;
    bool r = true;
#pragma unroll
    for (int i = 0; i < 64; i++) r = r && (u[i] <= 1u);
    return r;
}

__device__ __forceinline__ void cp16(void* sdst, const void* gsrc) {
    uint32_t sa = (uint32_t)__cvta_generic_to_shared(sdst);
    asm volatile("cp.async.cg.shared.global [%0], [%1], 16;" :: "r"(sa), "l"(gsrc));
}
__device__ __forceinline__ void cp_commit() { asm volatile("cp.async.commit_group;"); }
__device__ __forceinline__ void cp_wait1()  { asm volatile("cp.async.wait_group 1;"); }

__device__ __forceinline__ float wred(float v) {
    v += __shfl_down_sync(0xffffffffu, v, 16);
    v += __shfl_down_sync(0xffffffffu, v, 8);
    v += __shfl_down_sync(0xffffffffu, v, 4);
    v += __shfl_down_sync(0xffffffffu, v, 2);
    v += __shfl_down_sync(0xffffffffu, v, 1);
    return v;
}

__global__ __launch_bounds__(TPB, 2)
void match_kernel(const void* __restrict__ bigA, const void* __restrict__ bigB,
                  const int* __restrict__ gpn, float* __restrict__ out,
                  int N, int GMAX)
{
    const bool a_is_gt = looks_like_gt(bigA);
    const float* __restrict__ seg = (const float*)(a_is_gt ? bigB : bigA);
    const int*   __restrict__ gt  = (const int*)  (a_is_gt ? bigA : bigB);

    __shared__ float s_seg[NST][PIX * KK];    // [px][k]   10.5KB/stage
    __shared__ float s_gt [NST][GROW * PIX];  // [g][px]   11KB/stage
    __shared__ float s_red[NENT];
    __shared__ int   s_last;

    const int tid   = threadIdx.x;
    const int lane  = tid & 31;
    const int wid   = tid >> 5;            // 0..13
    const int half  = wid / 7;             // 0: g 0-10, 1: g 11-21(dummy)
    const int k0    = (wid % 7) * 3;
    const int gbase = half * GSP;

    float S0[GSP], S1[GSP], S2[GSP];
    float A0 = 0.f, A1 = 0.f, A2 = 0.f;    // accumulated by half 0 only
#pragma unroll
    for (int g = 0; g < GSP; g++) { S0[g] = 0.f; S1[g] = 0.f; S2[g] = 0.f; }

    // gt rows g >= GMAX (incl. dummy row 21) stay float 0 forever
    if (GMAX < GROW) {
        for (int i = tid; i < (GROW - GMAX) * PIX; i += TPB) {
            const int g = GMAX + i / PIX, c = i % PIX;
#pragma unroll
            for (int b = 0; b < NST; b++) s_gt[b][g * PIX + c] = 0.0f;
        }
        __syncthreads();
    }

    const int  ntiles   = (N + PIX - 1) / PIX;
    const bool fastN    = ((N & 3) == 0);
    const int  myntiles = (ntiles > (int)blockIdx.x)
                        ? (ntiles - blockIdx.x + gridDim.x - 1) / gridDim.x : 0;

    auto load_tile = [&](int it) {
        const int t = blockIdx.x + it * gridDim.x;
        if (t < ntiles) {
            const int       b    = it % NST;
            const int       base = t * PIX;
            const long long tb   = (long long)t * (PIX * KK);
            if (fastN && base + PIX <= N) {
#pragma unroll
                for (int j = 0; j < 2; j++) {            // 672 float4 of seg
                    const int i = tid + j * TPB;
                    if (i < PIX * KK / 4)
                        cp16(&s_seg[b][i * 4], seg + tb + i * 4);
                }
#pragma unroll
                for (int j = 0; j < 2; j++) {            // GMAX*32 int4 of gt
                    const int s = tid + j * TPB;         // 2*448 >= 672 slots
                    if (s < GMAX * 32) {
                        const int g = s >> 5, c = s & 31;
                        cp16((int*)s_gt[b] + g * PIX + c * 4,
                             gt + (long long)g * N + base + c * 4);
                    }
                }
            } else {                                     // generic tail
                const long long NKll = (long long)N * KK;
                for (int i = tid; i < PIX * KK; i += TPB) {
                    const long long idx = tb + i;
                    s_seg[b][i] = (idx < NKll) ? seg[idx] : 0.5f;  // pad: d=0
                }
                for (int s = tid; s < GMAX * PIX; s += TPB) {
                    const int g = s / PIX, c = s % PIX, p = base + c;
                    ((int*)s_gt[b])[g * PIX + c] =
                        (p < N) ? gt[(long long)g * N + p] : 0;
                }
            }
        }
        cp_commit();   // always commit: keeps wait_group accounting aligned
    };

    // Lane owns 2 consecutive pixels per 64-px subtile; this warp's g-range.
    auto compute_tile = [&](int buf) {
#pragma unroll
        for (int h = 0; h < 2; h++) {
            const int px0 = h * 64 + (lane << 1);
            float d0[2], d1[2], d2[2];
#pragma unroll
            for (int j = 0; j < 2; j++) {
                const int pb = (px0 + j) * KK;
                float s, l1;
                s  = s_seg[buf][pb + k0];
                l1 = __log2f(1.0f - s + EPSF);
                d0[j] = __log2f(s + EPSF) - l1;  A0 += l1;
                s  = s_seg[buf][pb + k0 + 1];
                l1 = __log2f(1.0f - s + EPSF);
                d1[j] = __log2f(s + EPSF) - l1;  A1 += l1;
                s  = s_seg[buf][pb + k0 + 2];
                l1 = __log2f(1.0f - s + EPSF);
                d2[j] = __log2f(s + EPSF) - l1;  A2 += l1;
            }
            const float2* gp = (const float2*)&s_gt[buf][gbase * PIX + px0];
#pragma unroll
            for (int g = 0; g < GSP; g++) {
                const float2 gv = gp[g * (PIX / 2)];
                S0[g] = fmaf(gv.x, d0[0], S0[g]);
                S0[g] = fmaf(gv.y, d0[1], S0[g]);
                S1[g] = fmaf(gv.x, d1[0], S1[g]);
                S1[g] = fmaf(gv.y, d1[1], S1[g]);
                S2[g] = fmaf(gv.x, d2[0], S2[g]);
                S2[g] = fmaf(gv.y, d2[1], S2[g]);
            }
        }
    };

    load_tile(0);
    load_tile(1);

    for (int it = 0; it < myntiles; it++) {
        const int buf = it % NST;

        cp_wait1();          // tile it resident (<=1 younger group pending)
        __syncthreads();     // smem visible; prior compute on ring buffer done

        load_tile(it + 2);   // issue 2-ahead into the just-freed buffer

        // convert this tile's gt ints -> floats in place (int4 granularity)
        {
            const int n4 = GMAX * (PIX / 4);
            for (int i = tid; i < n4; i += TPB) {
                int4 v = ((int4*)s_gt[buf])[i];
                ((float4*)s_gt[buf])[i] =
                    make_float4((float)v.x, (float)v.y, (float)v.z, (float)v.w);
            }
        }
        __syncthreads();     // converted floats visible to all warps

        compute_tile(buf);
    }

    // ---- warp reduce (lanes = pixel pairs) -> atomic accumulate ----
#pragma unroll
    for (int g = 0; g < GSP; g++) {
        const int gg = gbase + g;
        float v0 = wred(S0[g]), v1 = wred(S1[g]), v2 = wred(S2[g]);
        if (lane == 0 && gg < KK) {
            atomicAdd(&g_acc[(k0    ) * ROWW + gg], v0);
            atomicAdd(&g_acc[(k0 + 1) * ROWW + gg], v1);
            atomicAdd(&g_acc[(k0 + 2) * ROWW + gg], v2);
        }
    }
    if (half == 0) {    // A accumulated once (halves compute identical l1 sums)
        float a0 = wred(A0), a1 = wred(A1), a2 = wred(A2);
        if (lane == 0) {
            atomicAdd(&g_acc[(k0    ) * ROWW + KK], a0);
            atomicAdd(&g_acc[(k0 + 1) * ROWW + KK], a1);
            atomicAdd(&g_acc[(k0 + 2) * ROWW + KK], a2);
        }
    }

    __threadfence();
    __syncthreads();
    if (tid == 0)
        s_last = (atomicAdd(&g_ctr, 1) == (int)gridDim.x - 1) ? 1 : 0;
    __syncthreads();
    if (!s_last) return;
    __threadfence();

    // ---- last CTA: finalize ----
    for (int e = tid; e < NENT; e += TPB) {
        s_red[e] = __ldcg(&g_acc[e]);
        g_acc[e] = 0.0f;                  // reset for next graph replay
    }
    __syncthreads();

    int G = GMAX;
    if (gpn != nullptr) {
        const int gi = gpn[0];
        if (gi >= 1 && gi <= GMAX) G = gi;
        else {
            const float gfv = __int_as_float(gi);
            if (gfv >= 1.0f && gfv <= (float)GMAX && gfv == floorf(gfv))
                G = (int)gfv;
        }
    }

    __shared__ int   m_[KK];
    __shared__ float val[KK];
    __shared__ int   bestk[KK];

    if (tid < KK) {   // argmax_g S == argmin_g ce (first occurrence, strict >)
        int   best = 0;
        float bv   = s_red[tid * ROWW + 0];
        for (int g = 1; g < G; g++) {
            const float v = s_red[tid * ROWW + g];
            if (v > bv) { bv = v; best = g; }
        }
        m_[tid]  = best;
        val[tid] = s_red[tid * ROWW + KK] + bv;  // larger == smaller ce_val
    }
    __syncthreads();

    if (tid == 0) {
        int maxi = 0;
        for (int k = 0; k < KK; k++) if (m_[k] > maxi) maxi = m_[k];
        maxi += 1;
        for (int g = 0; g < G; g++) {
            float bb = -3.4e38f;
            int   bk = -1;
            for (int k = 0; k < KK; k++)
                if (m_[k] == g && val[k] > bb) { bb = val[k]; bk = k; }
            bestk[g] = bk;
        }
        for (int k = 0; k < KK; k++)
            out[k] = (float)((bestk[m_[k]] == k) ? m_[k] : maxi);
        g_ctr = 0;
    }
}

extern "C" void kernel_launch(void* const* d_in, const int* in_sizes, int n_in,
                              void* d_out, int out_size)
{
    int scalar_idx = -1;
    for (int i = 0; i < n_in; i++)
        if (in_sizes[i] == 1) { scalar_idx = i; break; }

    int big[2] = {-1, -1};
    int nb = 0;
    for (int i = 0; i < n_in && nb < 2; i++)
        if (i != scalar_idx) big[nb++] = i;

    const void* A   = d_in[big[0]];
    const void* B   = d_in[big[1]];
    const int*  gpn = (scalar_idx >= 0) ? (const int*)d_in[scalar_idx] : nullptr;

    const int bigsize = in_sizes[big[0]];
    int N    = bigsize / KK;
    int GMAX = (N > 0) ? (bigsize / N) : KK;
    if (GMAX > KK) GMAX = KK;
    if (GMAX < 1)  GMAX = 1;

    match_kernel<<<NBLK, TPB>>>(A, B, gpn, (float*)d_out, N, GMAX);
}